// round 1
// baseline (speedup 1.0000x reference)
#include <cuda_runtime.h>
#include <cstddef>

// Problem shape (fixed by dataset)
#define BB 16
#define SS 2048
#define DD 512

// GEMM tiling
#define BM 128
#define BN 128
#define BK 16
#define TM 8
#define TN 8
#define NTHREADS 256   // (BM/TM)*(BN/TN)

// Scratch for projected q, k  (2 x 64 MB, __device__ globals = allowed scratch)
__device__ float g_q[(size_t)BB * SS * DD];
__device__ float g_k[(size_t)BB * SS * DD];

// ---------------------------------------------------------------------------
// Tiled SGEMM.
//   C[m,n] = sum_k A[m,k] * B'[k,n] (+ bias)
//   B_IS_NK = true : B is stored [N,K] row-major (NT gemm: C = A * B^T)
//   B_IS_NK = false: B is stored [K,N] row-major (NN gemm)
//   BIAS_MODE: 0 = none, 1 = vector bias[n], 2 = matrix bias[m*N + n] (ld = N)
// All of M,N multiples of 128; K multiple of 16 (holds for every call here).
// Batched over blockIdx.z with element strides.
// ---------------------------------------------------------------------------
template <int BIAS_MODE, bool B_IS_NK>
__global__ __launch_bounds__(NTHREADS)
void sgemm_kernel(const float* __restrict__ Ag, const float* __restrict__ Bg,
                  const float* __restrict__ biasg, float* __restrict__ Cg,
                  int M, int N, int K,
                  size_t strideA, size_t strideB, size_t strideC)
{
    const float* A  = Ag + (size_t)blockIdx.z * strideA;
    const float* Bp = Bg + (size_t)blockIdx.z * strideB;
    float*       C  = Cg + (size_t)blockIdx.z * strideC;

    __shared__ float As[BK][BM];
    __shared__ float Bs[BK][BN];

    const int tid = threadIdx.x;
    const int tx  = tid & 15;        // 0..15  -> column group
    const int ty  = tid >> 4;        // 0..15  -> row group
    const int row0 = blockIdx.y * BM;
    const int col0 = blockIdx.x * BN;

    float acc[TM][TN] = {};

    for (int k0 = 0; k0 < K; k0 += BK) {
        // ---- load A tile [BM x BK], store transposed As[k][m] ----
        #pragma unroll
        for (int l = 0; l < 2; ++l) {
            int f = tid + l * NTHREADS;          // 0..511 float4 index
            int r = f >> 2;                      // 0..127 tile row
            int c = (f & 3) << 2;                // 0,4,8,12
            float4 v = *reinterpret_cast<const float4*>(
                &A[(size_t)(row0 + r) * K + k0 + c]);
            As[c + 0][r] = v.x; As[c + 1][r] = v.y;
            As[c + 2][r] = v.z; As[c + 3][r] = v.w;
        }
        // ---- load B tile ----
        if (B_IS_NK) {
            // B is [N,K]: tile [BN x BK], transpose into Bs[k][n]
            #pragma unroll
            for (int l = 0; l < 2; ++l) {
                int f = tid + l * NTHREADS;
                int r = f >> 2;
                int c = (f & 3) << 2;
                float4 v = *reinterpret_cast<const float4*>(
                    &Bp[(size_t)(col0 + r) * K + k0 + c]);
                Bs[c + 0][r] = v.x; Bs[c + 1][r] = v.y;
                Bs[c + 2][r] = v.z; Bs[c + 3][r] = v.w;
            }
        } else {
            // B is [K,N]: tile [BK x BN], direct copy
            #pragma unroll
            for (int l = 0; l < 2; ++l) {
                int f = tid + l * NTHREADS;
                int r = f >> 5;                  // 0..15 tile row (k)
                int c = (f & 31) << 2;           // 0..124 step 4
                *reinterpret_cast<float4*>(&Bs[r][c]) =
                    *reinterpret_cast<const float4*>(
                        &Bp[(size_t)(k0 + r) * N + col0 + c]);
            }
        }
        __syncthreads();

        // ---- compute ----
        #pragma unroll
        for (int kk = 0; kk < BK; ++kk) {
            float ra[TM], rb[TN];
            #pragma unroll
            for (int i = 0; i < TM; i += 4)
                *reinterpret_cast<float4*>(&ra[i]) =
                    *reinterpret_cast<const float4*>(&As[kk][ty * TM + i]);
            #pragma unroll
            for (int j = 0; j < TN; j += 4)
                *reinterpret_cast<float4*>(&rb[j]) =
                    *reinterpret_cast<const float4*>(&Bs[kk][tx * TN + j]);
            #pragma unroll
            for (int i = 0; i < TM; ++i)
                #pragma unroll
                for (int j = 0; j < TN; ++j)
                    acc[i][j] += ra[i] * rb[j];
        }
        __syncthreads();
    }

    // ---- epilogue: bias + store (float4) ----
    #pragma unroll
    for (int i = 0; i < TM; ++i) {
        int r = row0 + ty * TM + i;
        #pragma unroll
        for (int j = 0; j < TN; j += 4) {
            int c = col0 + tx * TN + j;
            float4 v = make_float4(acc[i][j], acc[i][j + 1],
                                   acc[i][j + 2], acc[i][j + 3]);
            if (BIAS_MODE == 1) {
                float4 bv = *reinterpret_cast<const float4*>(&biasg[c]);
                v.x += bv.x; v.y += bv.y; v.z += bv.z; v.w += bv.w;
            } else if (BIAS_MODE == 2) {
                float4 bv = *reinterpret_cast<const float4*>(
                    &biasg[(size_t)r * N + c]);
                v.x += bv.x; v.y += bv.y; v.z += bv.z; v.w += bv.w;
            }
            *reinterpret_cast<float4*>(&C[(size_t)r * N + c]) = v;
        }
    }
}

// ---------------------------------------------------------------------------
// In-place row softmax over [B*S, S] with S = 2048, one block per row.
// 256 threads x 8 elements each, registers only, two block reductions.
// ---------------------------------------------------------------------------
__global__ __launch_bounds__(256)
void softmax_rows_kernel(float* __restrict__ attn)
{
    const size_t row = blockIdx.x;
    float* p = attn + row * (size_t)SS;
    const int t = threadIdx.x;
    const int lane = t & 31;
    const int warp = t >> 5;

    float v[8];
    float4 a = *reinterpret_cast<const float4*>(&p[t * 8]);
    float4 b = *reinterpret_cast<const float4*>(&p[t * 8 + 4]);
    v[0] = a.x; v[1] = a.y; v[2] = a.z; v[3] = a.w;
    v[4] = b.x; v[5] = b.y; v[6] = b.z; v[7] = b.w;

    __shared__ float red_max[8];
    __shared__ float red_sum[8];
    __shared__ float bcast[2];

    // --- max ---
    float m = v[0];
    #pragma unroll
    for (int i = 1; i < 8; ++i) m = fmaxf(m, v[i]);
    #pragma unroll
    for (int off = 16; off > 0; off >>= 1)
        m = fmaxf(m, __shfl_xor_sync(0xFFFFFFFFu, m, off));
    if (lane == 0) red_max[warp] = m;
    __syncthreads();
    if (t == 0) {
        float mm = red_max[0];
        #pragma unroll
        for (int w = 1; w < 8; ++w) mm = fmaxf(mm, red_max[w]);
        bcast[0] = mm;
    }
    __syncthreads();
    const float row_max = bcast[0];

    // --- exp + sum ---
    float s = 0.f;
    #pragma unroll
    for (int i = 0; i < 8; ++i) {
        v[i] = expf(v[i] - row_max);
        s += v[i];
    }
    #pragma unroll
    for (int off = 16; off > 0; off >>= 1)
        s += __shfl_xor_sync(0xFFFFFFFFu, s, off);
    if (lane == 0) red_sum[warp] = s;
    __syncthreads();
    if (t == 0) {
        float ss = red_sum[0];
        #pragma unroll
        for (int w = 1; w < 8; ++w) ss += red_sum[w];
        bcast[1] = 1.f / ss;
    }
    __syncthreads();
    const float inv = bcast[1];

    #pragma unroll
    for (int i = 0; i < 8; ++i) v[i] *= inv;
    a = make_float4(v[0], v[1], v[2], v[3]);
    b = make_float4(v[4], v[5], v[6], v[7]);
    *reinterpret_cast<float4*>(&p[t * 8])     = a;
    *reinterpret_cast<float4*>(&p[t * 8 + 4]) = b;
}

// ---------------------------------------------------------------------------
// Host launcher
// ---------------------------------------------------------------------------
extern "C" void kernel_launch(void* const* d_in, const int* in_sizes, int n_in,
                              void* d_out, int out_size)
{
    (void)in_sizes; (void)n_in; (void)out_size;
    const float* query     = (const float*)d_in[0];   // [B,S,D]
    const float* key       = (const float*)d_in[1];   // [B,S,D]
    const float* value     = (const float*)d_in[2];   // [B,S,D]
    const float* attn_bias = (const float*)d_in[3];   // [1,S,S]
    const float* Wq        = (const float*)d_in[4];   // [D,D]
    const float* bq        = (const float*)d_in[5];   // [D]
    const float* Wk        = (const float*)d_in[6];   // [D,D]
    const float* bk        = (const float*)d_in[7];   // [D]

    float* out  = (float*)d_out;                          // [B,S,D]
    float* attn = out + (size_t)BB * SS * DD;             // [B,S,S]

    float *qbuf = nullptr, *kbuf = nullptr;
    cudaGetSymbolAddress((void**)&qbuf, g_q);
    cudaGetSymbolAddress((void**)&kbuf, g_k);

    // 1) q = query @ Wq^T + bq   (M = B*S, N = D, K = D; NT, vector bias)
    {
        dim3 grid(DD / BN, (BB * SS) / BM, 1);
        sgemm_kernel<1, true><<<grid, NTHREADS>>>(
            query, Wq, bq, qbuf, BB * SS, DD, DD, 0, 0, 0);
    }
    // 2) k = key @ Wk^T + bk
    {
        dim3 grid(DD / BN, (BB * SS) / BM, 1);
        sgemm_kernel<1, true><<<grid, NTHREADS>>>(
            key, Wk, bk, kbuf, BB * SS, DD, DD, 0, 0, 0);
    }
    // 3) scores = q @ k^T + attn_bias, written into attention output region
    //    batched over B (M = N = S, K = D; NT, matrix bias shared across batch)
    {
        dim3 grid(SS / BN, SS / BM, BB);
        sgemm_kernel<2, true><<<grid, NTHREADS>>>(
            qbuf, kbuf, attn_bias, attn, SS, SS, DD,
            (size_t)SS * DD, (size_t)SS * DD, (size_t)SS * SS);
    }
    // 4) softmax rows in place
    {
        softmax_rows_kernel<<<BB * SS, 256>>>(attn);
    }
    // 5) out = attention @ value (M = S, N = D, K = S; NN, no bias)
    {
        dim3 grid(DD / BN, SS / BM, BB);
        sgemm_kernel<0, false><<<grid, NTHREADS>>>(
            attn, value, nullptr, out, SS, DD, SS,
            (size_t)SS * SS, (size_t)SS * DD, (size_t)SS * DD);
    }
}

// round 2
// speedup vs baseline: 1.0022x; 1.0022x over previous
#include <cuda_runtime.h>
#include <cstddef>

// Problem shape (fixed by dataset)
#define BB 16
#define SS 2048
#define DD 512

// GEMM tiling
#define BM 128
#define BN 128
#define BK 16
#define TM 8
#define TN 8
#define NTHREADS 256   // (BM/TM)*(BN/TN)

// Scratch for projected q, k  (2 x 64 MB, __device__ globals = allowed scratch)
__device__ float g_q[(size_t)BB * SS * DD];
__device__ float g_k[(size_t)BB * SS * DD];

// ---------------------------------------------------------------------------
// Tiled SGEMM.
//   C[m,n] = sum_k A[m,k] * B'[k,n] (+ bias)
//   B_IS_NK = true : B is stored [N,K] row-major (NT gemm: C = A * B^T)
//   B_IS_NK = false: B is stored [K,N] row-major (NN gemm)
//   BIAS_MODE: 0 = none, 1 = vector bias[n], 2 = matrix bias[m*N + n] (ld = N)
// All of M,N multiples of 128; K multiple of 16 (holds for every call here).
// Batched over blockIdx.z with element strides.
// ---------------------------------------------------------------------------
template <int BIAS_MODE, bool B_IS_NK>
__global__ __launch_bounds__(NTHREADS)
void sgemm_kernel(const float* __restrict__ Ag, const float* __restrict__ Bg,
                  const float* __restrict__ biasg, float* __restrict__ Cg,
                  int M, int N, int K,
                  size_t strideA, size_t strideB, size_t strideC)
{
    const float* A  = Ag + (size_t)blockIdx.z * strideA;
    const float* Bp = Bg + (size_t)blockIdx.z * strideB;
    float*       C  = Cg + (size_t)blockIdx.z * strideC;

    __shared__ float As[BK][BM];
    __shared__ float Bs[BK][BN];

    const int tid = threadIdx.x;
    const int tx  = tid & 15;        // 0..15  -> column group
    const int ty  = tid >> 4;        // 0..15  -> row group
    const int row0 = blockIdx.y * BM;
    const int col0 = blockIdx.x * BN;

    float acc[TM][TN] = {};

    for (int k0 = 0; k0 < K; k0 += BK) {
        // ---- load A tile [BM x BK], store transposed As[k][m] ----
        #pragma unroll
        for (int l = 0; l < 2; ++l) {
            int f = tid + l * NTHREADS;          // 0..511 float4 index
            int r = f >> 2;                      // 0..127 tile row
            int c = (f & 3) << 2;                // 0,4,8,12
            float4 v = *reinterpret_cast<const float4*>(
                &A[(size_t)(row0 + r) * K + k0 + c]);
            As[c + 0][r] = v.x; As[c + 1][r] = v.y;
            As[c + 2][r] = v.z; As[c + 3][r] = v.w;
        }
        // ---- load B tile ----
        if (B_IS_NK) {
            // B is [N,K]: tile [BN x BK], transpose into Bs[k][n]
            #pragma unroll
            for (int l = 0; l < 2; ++l) {
                int f = tid + l * NTHREADS;
                int r = f >> 2;
                int c = (f & 3) << 2;
                float4 v = *reinterpret_cast<const float4*>(
                    &Bp[(size_t)(col0 + r) * K + k0 + c]);
                Bs[c + 0][r] = v.x; Bs[c + 1][r] = v.y;
                Bs[c + 2][r] = v.z; Bs[c + 3][r] = v.w;
            }
        } else {
            // B is [K,N]: tile [BK x BN], direct copy
            #pragma unroll
            for (int l = 0; l < 2; ++l) {
                int f = tid + l * NTHREADS;
                int r = f >> 5;                  // 0..15 tile row (k)
                int c = (f & 31) << 2;           // 0..124 step 4
                *reinterpret_cast<float4*>(&Bs[r][c]) =
                    *reinterpret_cast<const float4*>(
                        &Bp[(size_t)(k0 + r) * N + col0 + c]);
            }
        }
        __syncthreads();

        // ---- compute ----
        #pragma unroll
        for (int kk = 0; kk < BK; ++kk) {
            float ra[TM], rb[TN];
            #pragma unroll
            for (int i = 0; i < TM; i += 4)
                *reinterpret_cast<float4*>(&ra[i]) =
                    *reinterpret_cast<const float4*>(&As[kk][ty * TM + i]);
            #pragma unroll
            for (int j = 0; j < TN; j += 4)
                *reinterpret_cast<float4*>(&rb[j]) =
                    *reinterpret_cast<const float4*>(&Bs[kk][tx * TN + j]);
            #pragma unroll
            for (int i = 0; i < TM; ++i)
                #pragma unroll
                for (int j = 0; j < TN; ++j)
                    acc[i][j] += ra[i] * rb[j];
        }
        __syncthreads();
    }

    // ---- epilogue: bias + store (float4) ----
    #pragma unroll
    for (int i = 0; i < TM; ++i) {
        int r = row0 + ty * TM + i;
        #pragma unroll
        for (int j = 0; j < TN; j += 4) {
            int c = col0 + tx * TN + j;
            float4 v = make_float4(acc[i][j], acc[i][j + 1],
                                   acc[i][j + 2], acc[i][j + 3]);
            if (BIAS_MODE == 1) {
                float4 bv = *reinterpret_cast<const float4*>(&biasg[c]);
                v.x += bv.x; v.y += bv.y; v.z += bv.z; v.w += bv.w;
            } else if (BIAS_MODE == 2) {
                float4 bv = *reinterpret_cast<const float4*>(
                    &biasg[(size_t)r * N + c]);
                v.x += bv.x; v.y += bv.y; v.z += bv.z; v.w += bv.w;
            }
            *reinterpret_cast<float4*>(&C[(size_t)r * N + c]) = v;
        }
    }
}

// ---------------------------------------------------------------------------
// In-place row softmax over [B*S, S] with S = 2048, one block per row.
// 256 threads x 8 elements each, registers only, two block reductions.
// ---------------------------------------------------------------------------
__global__ __launch_bounds__(256)
void softmax_rows_kernel(float* __restrict__ attn)
{
    const size_t row = blockIdx.x;
    float* p = attn + row * (size_t)SS;
    const int t = threadIdx.x;
    const int lane = t & 31;
    const int warp = t >> 5;

    float v[8];
    float4 a = *reinterpret_cast<const float4*>(&p[t * 8]);
    float4 b = *reinterpret_cast<const float4*>(&p[t * 8 + 4]);
    v[0] = a.x; v[1] = a.y; v[2] = a.z; v[3] = a.w;
    v[4] = b.x; v[5] = b.y; v[6] = b.z; v[7] = b.w;

    __shared__ float red_max[8];
    __shared__ float red_sum[8];
    __shared__ float bcast[2];

    // --- max ---
    float m = v[0];
    #pragma unroll
    for (int i = 1; i < 8; ++i) m = fmaxf(m, v[i]);
    #pragma unroll
    for (int off = 16; off > 0; off >>= 1)
        m = fmaxf(m, __shfl_xor_sync(0xFFFFFFFFu, m, off));
    if (lane == 0) red_max[warp] = m;
    __syncthreads();
    if (t == 0) {
        float mm = red_max[0];
        #pragma unroll
        for (int w = 1; w < 8; ++w) mm = fmaxf(mm, red_max[w]);
        bcast[0] = mm;
    }
    __syncthreads();
    const float row_max = bcast[0];

    // --- exp + sum ---
    float s = 0.f;
    #pragma unroll
    for (int i = 0; i < 8; ++i) {
        v[i] = expf(v[i] - row_max);
        s += v[i];
    }
    #pragma unroll
    for (int off = 16; off > 0; off >>= 1)
        s += __shfl_xor_sync(0xFFFFFFFFu, s, off);
    if (lane == 0) red_sum[warp] = s;
    __syncthreads();
    if (t == 0) {
        float ss = red_sum[0];
        #pragma unroll
        for (int w = 1; w < 8; ++w) ss += red_sum[w];
        bcast[1] = 1.f / ss;
    }
    __syncthreads();
    const float inv = bcast[1];

    #pragma unroll
    for (int i = 0; i < 8; ++i) v[i] *= inv;
    a = make_float4(v[0], v[1], v[2], v[3]);
    b = make_float4(v[4], v[5], v[6], v[7]);
    *reinterpret_cast<float4*>(&p[t * 8])     = a;
    *reinterpret_cast<float4*>(&p[t * 8 + 4]) = b;
}

// ---------------------------------------------------------------------------
// Host launcher
// ---------------------------------------------------------------------------
extern "C" void kernel_launch(void* const* d_in, const int* in_sizes, int n_in,
                              void* d_out, int out_size)
{
    (void)in_sizes; (void)n_in; (void)out_size;
    const float* query     = (const float*)d_in[0];   // [B,S,D]
    const float* key       = (const float*)d_in[1];   // [B,S,D]
    const float* value     = (const float*)d_in[2];   // [B,S,D]
    const float* attn_bias = (const float*)d_in[3];   // [1,S,S]
    const float* Wq        = (const float*)d_in[4];   // [D,D]
    const float* bq        = (const float*)d_in[5];   // [D]
    const float* Wk        = (const float*)d_in[6];   // [D,D]
    const float* bk        = (const float*)d_in[7];   // [D]

    float* out  = (float*)d_out;                          // [B,S,D]
    float* attn = out + (size_t)BB * SS * DD;             // [B,S,S]

    float *qbuf = nullptr, *kbuf = nullptr;
    cudaGetSymbolAddress((void**)&qbuf, g_q);
    cudaGetSymbolAddress((void**)&kbuf, g_k);

    // 1) q = query @ Wq^T + bq   (M = B*S, N = D, K = D; NT, vector bias)
    {
        dim3 grid(DD / BN, (BB * SS) / BM, 1);
        sgemm_kernel<1, true><<<grid, NTHREADS>>>(
            query, Wq, bq, qbuf, BB * SS, DD, DD, 0, 0, 0);
    }
    // 2) k = key @ Wk^T + bk
    {
        dim3 grid(DD / BN, (BB * SS) / BM, 1);
        sgemm_kernel<1, true><<<grid, NTHREADS>>>(
            key, Wk, bk, kbuf, BB * SS, DD, DD, 0, 0, 0);
    }
    // 3) scores = q @ k^T + attn_bias, written into attention output region
    //    batched over B (M = N = S, K = D; NT, matrix bias shared across batch)
    {
        dim3 grid(SS / BN, SS / BM, BB);
        sgemm_kernel<2, true><<<grid, NTHREADS>>>(
            qbuf, kbuf, attn_bias, attn, SS, SS, DD,
            (size_t)SS * DD, (size_t)SS * DD, (size_t)SS * SS);
    }
    // 4) softmax rows in place
    {
        softmax_rows_kernel<<<BB * SS, 256>>>(attn);
    }
    // 5) out = attention @ value (M = S, N = D, K = S; NN, no bias)
    {
        dim3 grid(DD / BN, SS / BM, BB);
        sgemm_kernel<0, false><<<grid, NTHREADS>>>(
            attn, value, nullptr, out, SS, DD, SS,
            (size_t)SS * SS, (size_t)SS * DD, (size_t)SS * DD);
    }
}

// round 5
// speedup vs baseline: 2.2317x; 2.2268x over previous
#include <cuda_runtime.h>
#include <cuda_bf16.h>
#include <cstdint>
#include <cstddef>

#define BB 16
#define SS 2048
#define DD 512
#define KPP 1536   // 3*DD packed K (projections, scores)
#define KPA 6144   // 3*SS packed K (PV)

// ---------------- scratch (__device__ globals) ------------------------------
__device__ __align__(256) __nv_bfloat16 g_aq[(size_t)BB * SS * KPP]; // query A-pack
__device__ __align__(256) __nv_bfloat16 g_ak[(size_t)BB * SS * KPP]; // key   A-pack
__device__ __align__(256) __nv_bfloat16 g_wq[(size_t)DD * KPP];      // Wq B-pack
__device__ __align__(256) __nv_bfloat16 g_wk[(size_t)DD * KPP];      // Wk B-pack
__device__ __align__(256) __nv_bfloat16 g_qp[(size_t)BB * SS * KPP]; // q A-pack
__device__ __align__(256) __nv_bfloat16 g_kp[(size_t)BB * SS * KPP]; // k B-pack
__device__ __align__(256) __nv_bfloat16 g_vp[(size_t)BB * DD * KPA]; // value^T B-pack
__device__ __align__(256) __nv_bfloat16 g_ap[(size_t)BB * SS * KPA]; // attention A-pack

// ---------------- helpers ---------------------------------------------------
__device__ __forceinline__ uint32_t smem_u32_of(const void* p) {
    uint32_t a;
    asm("{ .reg .u64 t; cvta.to.shared.u64 t, %1; cvt.u32.u64 %0, t; }"
        : "=r"(a) : "l"(p));
    return a;
}
__device__ __forceinline__ void cp_async16(uint32_t dst, const void* src) {
    asm volatile("cp.async.cg.shared.global [%0], [%1], 16;"
                 :: "r"(dst), "l"(src) : "memory");
}
__device__ __forceinline__ void ldsm4(uint32_t (&r)[4], uint32_t addr) {
    asm volatile("ldmatrix.sync.aligned.m8n8.x4.shared.b16 {%0,%1,%2,%3}, [%4];"
                 : "=r"(r[0]), "=r"(r[1]), "=r"(r[2]), "=r"(r[3]) : "r"(addr));
}
__device__ __forceinline__ void mma16816(float (&d)[4], const uint32_t (&a)[4],
                                         uint32_t b0, uint32_t b1) {
    asm volatile("mma.sync.aligned.m16n8k16.row.col.f32.bf16.bf16.f32 "
                 "{%0,%1,%2,%3}, {%4,%5,%6,%7}, {%8,%9}, {%0,%1,%2,%3};"
                 : "+f"(d[0]), "+f"(d[1]), "+f"(d[2]), "+f"(d[3])
                 : "r"(a[0]), "r"(a[1]), "r"(a[2]), "r"(a[3]), "r"(b0), "r"(b1));
}
__device__ __forceinline__ void split2(float v, __nv_bfloat16& h, __nv_bfloat16& l) {
    h = __float2bfloat16(v);
    l = __float2bfloat16(v - __bfloat162float(h));
}

// ---------------- pack fp32 -> bf16x3 (row-major, K -> 3K) ------------------
// AMODE true: regions (hi, hi, lo); false: (hi, lo, hi)
template <bool AMODE>
__global__ __launch_bounds__(256)
void pack_kernel(const float* __restrict__ in, __nv_bfloat16* __restrict__ outp,
                 int K, size_t total)
{
    size_t i4 = ((size_t)blockIdx.x * 256 + threadIdx.x) * 4;
    if (i4 >= total) return;
    float4 v = *reinterpret_cast<const float4*>(&in[i4]);
    size_t row = i4 / (size_t)K;
    int col = (int)(i4 - row * K);
    __align__(8) __nv_bfloat16 h[4], l[4];
    split2(v.x, h[0], l[0]); split2(v.y, h[1], l[1]);
    split2(v.z, h[2], l[2]); split2(v.w, h[3], l[3]);
    uint2 hh = *reinterpret_cast<uint2*>(h);
    uint2 ll = *reinterpret_cast<uint2*>(l);
    __nv_bfloat16* rp = outp + row * (size_t)(3 * K) + col;
    *reinterpret_cast<uint2*>(rp)         = hh;
    *reinterpret_cast<uint2*>(rp + K)     = AMODE ? hh : ll;
    *reinterpret_cast<uint2*>(rp + 2 * K) = AMODE ? ll : hh;
}

// ---------------- value transpose + B-pack ----------------------------------
// value [B,S,D] fp32 -> g_vp [B, D, 3S] bf16 regions (hi, lo, hi)
__global__ __launch_bounds__(256)
void vpack_kernel(const float* __restrict__ value)
{
    __shared__ float t[32][33];
    int b = blockIdx.z, d0 = blockIdx.x * 32, s0 = blockIdx.y * 32;
    const float* vb = value + (size_t)b * SS * DD;
    int tid = threadIdx.x;
    #pragma unroll
    for (int i = 0; i < 4; ++i) {
        int lin = tid + i * 256;
        int r = lin >> 5, c = lin & 31;       // r: s-offset, c: d-offset
        t[r][c] = vb[(size_t)(s0 + r) * DD + d0 + c];
    }
    __syncthreads();
    __nv_bfloat16* ob = g_vp + (size_t)b * DD * KPA;
    #pragma unroll
    for (int i = 0; i < 4; ++i) {
        int lin = tid + i * 256;
        int dr = lin >> 5, sc = lin & 31;
        float v = t[sc][dr];
        __nv_bfloat16 h, l;
        split2(v, h, l);
        size_t base = (size_t)(d0 + dr) * KPA + (s0 + sc);
        ob[base]          = h;
        ob[base + SS]     = l;
        ob[base + 2 * SS] = h;
    }
}

// ---------------- mma.sync GEMM: C[128x128] = A[128xKp] * B[128xKp]^T -------
// MODE 0: plain fp32 store (ldc = DD)          -> Cf   (PV)
// MODE 1: + biasm[r*SS + c], fp32 (ldc = SS)   -> Cf   (scores)
// MODE 2: + biasv[c], emit A-pack (hi,hi,lo)   -> Cp   (q projection)
// MODE 3: + biasv[c], emit B-pack (hi,lo,hi)   -> Cp   (k projection)
#define BM 128
#define BN 128
#define BKC 32
#define SST 40          // smem row stride in bf16 elems (80 bytes)

__device__ __forceinline__ void stage_load(
    const __nv_bfloat16* __restrict__ A, const __nv_bfloat16* __restrict__ B,
    int Kp, int row0, int col0, int k0,
    uint32_t aBase, uint32_t bBase, int tid)
{
    #pragma unroll
    for (int i = 0; i < 2; ++i) {
        int idx = tid + (i << 8);
        int r = idx >> 2, c = idx & 3;
        cp_async16(aBase + r * (SST * 2) + c * 16,
                   A + (size_t)(row0 + r) * Kp + k0 + c * 8);
    }
    #pragma unroll
    for (int i = 0; i < 2; ++i) {
        int idx = tid + (i << 8);
        int r = idx >> 2, c = idx & 3;
        cp_async16(bBase + r * (SST * 2) + c * 16,
                   B + (size_t)(col0 + r) * Kp + k0 + c * 8);
    }
    asm volatile("cp.async.commit_group;" ::: "memory");
}

template <int MODE>
__global__ __launch_bounds__(256, 2)
void gemm_mma(const __nv_bfloat16* __restrict__ Ag, const __nv_bfloat16* __restrict__ Bg,
              const float* __restrict__ biasv, const float* __restrict__ biasm,
              float* __restrict__ Cf, __nv_bfloat16* __restrict__ Cp,
              int Kp, size_t sA, size_t sB, size_t sC)
{
    __shared__ __nv_bfloat16 sAm[2][BM][SST];
    __shared__ __nv_bfloat16 sBm[2][BN][SST];

    const int tid = threadIdx.x;
    const int wid = tid >> 5, lane = tid & 31;
    const int row0 = blockIdx.y * BM, col0 = blockIdx.x * BN;
    const __nv_bfloat16* A = Ag + (size_t)blockIdx.z * sA;
    const __nv_bfloat16* B = Bg + (size_t)blockIdx.z * sB;
    const int wm = (wid & 3) * 32;      // warp M offset (4 warps)
    const int wn = (wid >> 2) * 64;     // warp N offset (2 warps)

    float acc[2][8][4];
    #pragma unroll
    for (int i = 0; i < 2; ++i)
        #pragma unroll
        for (int j = 0; j < 8; ++j)
            #pragma unroll
            for (int q = 0; q < 4; ++q) acc[i][j][q] = 0.f;

    uint32_t aS[2] = { smem_u32_of(&sAm[0][0][0]), smem_u32_of(&sAm[1][0][0]) };
    uint32_t bS[2] = { smem_u32_of(&sBm[0][0][0]), smem_u32_of(&sBm[1][0][0]) };

    const int CK = Kp / BKC;
    stage_load(A, B, Kp, row0, col0, 0, aS[0], bS[0], tid);

    for (int c = 0; c < CK; ++c) {
        if (c + 1 < CK) {
            stage_load(A, B, Kp, row0, col0, (c + 1) * BKC,
                       aS[(c + 1) & 1], bS[(c + 1) & 1], tid);
            asm volatile("cp.async.wait_group 1;" ::: "memory");
        } else {
            asm volatile("cp.async.wait_group 0;" ::: "memory");
        }
        __syncthreads();

        const int st = c & 1;
        #pragma unroll
        for (int kk = 0; kk < 2; ++kk) {
            uint32_t a[2][4], b[4][4];
            // A fragments: rows wm + (lane&15) (+16), col = kk*16 + ((lane>>4)<<3)
            {
                int arow = wm + (lane & 15);
                int acol = kk * 16 + ((lane >> 4) << 3);
                ldsm4(a[0], aS[st] + (uint32_t)(arow * (SST * 2) + acol * 2));
                ldsm4(a[1], aS[st] + (uint32_t)((arow + 16) * (SST * 2) + acol * 2));
            }
            // B fragments: 4 x4 loads cover n64
            {
                int brow = wn + (lane & 7) + ((lane >> 4) << 3);
                int bcol = kk * 16 + (((lane >> 3) & 1) << 3);
                #pragma unroll
                for (int p = 0; p < 4; ++p)
                    ldsm4(b[p], bS[st] + (uint32_t)((brow + p * 16) * (SST * 2) + bcol * 2));
            }
            #pragma unroll
            for (int mt = 0; mt < 2; ++mt)
                #pragma unroll
                for (int nt = 0; nt < 8; ++nt)
                    mma16816(acc[mt][nt], a[mt],
                             b[nt >> 1][(nt & 1) * 2], b[nt >> 1][(nt & 1) * 2 + 1]);
        }
        __syncthreads();
    }

    // ---- epilogue ----
    #pragma unroll
    for (int mt = 0; mt < 2; ++mt) {
        #pragma unroll
        for (int h = 0; h < 2; ++h) {
            const int r = row0 + wm + mt * 16 + (lane >> 2) + h * 8;
            if (MODE == 0) {
                float* dst = Cf + (size_t)blockIdx.z * sC + (size_t)r * DD;
                #pragma unroll
                for (int nt = 0; nt < 8; ++nt) {
                    int cg = col0 + wn + nt * 8 + (lane & 3) * 2;
                    float2 v = make_float2(acc[mt][nt][h * 2], acc[mt][nt][h * 2 + 1]);
                    *reinterpret_cast<float2*>(dst + cg) = v;
                }
            } else if (MODE == 1) {
                float* dst = Cf + (size_t)blockIdx.z * sC + (size_t)r * SS;
                const float* bm = biasm + (size_t)r * SS;
                #pragma unroll
                for (int nt = 0; nt < 8; ++nt) {
                    int cg = col0 + wn + nt * 8 + (lane & 3) * 2;
                    float2 b2 = *reinterpret_cast<const float2*>(bm + cg);
                    float2 v = make_float2(acc[mt][nt][h * 2] + b2.x,
                                           acc[mt][nt][h * 2 + 1] + b2.y);
                    *reinterpret_cast<float2*>(dst + cg) = v;
                }
            } else {
                __nv_bfloat16* rp = Cp + (size_t)r * KPP;
                #pragma unroll
                for (int nt = 0; nt < 8; ++nt) {
                    int cg = col0 + wn + nt * 8 + (lane & 3) * 2;
                    float2 b2 = *reinterpret_cast<const float2*>(biasv + cg);
                    float vx = acc[mt][nt][h * 2] + b2.x;
                    float vy = acc[mt][nt][h * 2 + 1] + b2.y;
                    __nv_bfloat16 h0, l0, h1, l1;
                    split2(vx, h0, l0); split2(vy, h1, l1);
                    __nv_bfloat162 hh(h0, h1), ll(l0, l1);
                    *reinterpret_cast<__nv_bfloat162*>(rp + cg)          = hh;
                    *reinterpret_cast<__nv_bfloat162*>(rp + DD + cg)     = (MODE == 2) ? hh : ll;
                    *reinterpret_cast<__nv_bfloat162*>(rp + 2 * DD + cg) = (MODE == 2) ? ll : hh;
                }
            }
        }
    }
}

// ---------------- softmax + A-pack emit -------------------------------------
__global__ __launch_bounds__(256)
void softmax_pack_kernel(float* __restrict__ attn)
{
    const size_t row = blockIdx.x;
    float* p = attn + row * (size_t)SS;
    const int t = threadIdx.x;
    const int lane = t & 31, warp = t >> 5;

    float v[8];
    float4 a = *reinterpret_cast<const float4*>(&p[t * 8]);
    float4 b = *reinterpret_cast<const float4*>(&p[t * 8 + 4]);
    v[0] = a.x; v[1] = a.y; v[2] = a.z; v[3] = a.w;
    v[4] = b.x; v[5] = b.y; v[6] = b.z; v[7] = b.w;

    __shared__ float red[8];
    __shared__ float bc[2];

    float m = v[0];
    #pragma unroll
    for (int i = 1; i < 8; ++i) m = fmaxf(m, v[i]);
    #pragma unroll
    for (int off = 16; off > 0; off >>= 1)
        m = fmaxf(m, __shfl_xor_sync(0xFFFFFFFFu, m, off));
    if (lane == 0) red[warp] = m;
    __syncthreads();
    if (t == 0) {
        float mm = red[0];
        #pragma unroll
        for (int w = 1; w < 8; ++w) mm = fmaxf(mm, red[w]);
        bc[0] = mm;
    }
    __syncthreads();
    const float rmax = bc[0];

    float s = 0.f;
    #pragma unroll
    for (int i = 0; i < 8; ++i) { v[i] = expf(v[i] - rmax); s += v[i]; }
    #pragma unroll
    for (int off = 16; off > 0; off >>= 1)
        s += __shfl_xor_sync(0xFFFFFFFFu, s, off);
    __syncthreads();
    if (lane == 0) red[warp] = s;
    __syncthreads();
    if (t == 0) {
        float ss = red[0];
        #pragma unroll
        for (int w = 1; w < 8; ++w) ss += red[w];
        bc[1] = 1.f / ss;
    }
    __syncthreads();
    const float inv = bc[1];

    __align__(16) __nv_bfloat16 h8[8], l8[8];
    #pragma unroll
    for (int i = 0; i < 8; ++i) {
        v[i] *= inv;
        split2(v[i], h8[i], l8[i]);
    }
    *reinterpret_cast<float4*>(&p[t * 8])     = make_float4(v[0], v[1], v[2], v[3]);
    *reinterpret_cast<float4*>(&p[t * 8 + 4]) = make_float4(v[4], v[5], v[6], v[7]);

    uint4 hv = *reinterpret_cast<uint4*>(h8);
    uint4 lv = *reinterpret_cast<uint4*>(l8);
    size_t base = row * (size_t)KPA + t * 8;
    *reinterpret_cast<uint4*>(&g_ap[base])          = hv;
    *reinterpret_cast<uint4*>(&g_ap[base + SS])     = hv;
    *reinterpret_cast<uint4*>(&g_ap[base + 2 * SS]) = lv;
}

// ---------------- host launcher ---------------------------------------------
extern "C" void kernel_launch(void* const* d_in, const int* in_sizes, int n_in,
                              void* d_out, int out_size)
{
    (void)in_sizes; (void)n_in; (void)out_size;
    const float* query     = (const float*)d_in[0];
    const float* key       = (const float*)d_in[1];
    const float* value     = (const float*)d_in[2];
    const float* attn_bias = (const float*)d_in[3];
    const float* Wq        = (const float*)d_in[4];
    const float* bq        = (const float*)d_in[5];
    const float* Wk        = (const float*)d_in[6];
    const float* bk        = (const float*)d_in[7];

    float* out  = (float*)d_out;
    float* attn = out + (size_t)BB * SS * DD;

    __nv_bfloat16 *aq, *ak, *wq, *wk, *qp, *kp, *vp, *ap;
    cudaGetSymbolAddress((void**)&aq, g_aq);
    cudaGetSymbolAddress((void**)&ak, g_ak);
    cudaGetSymbolAddress((void**)&wq, g_wq);
    cudaGetSymbolAddress((void**)&wk, g_wk);
    cudaGetSymbolAddress((void**)&qp, g_qp);
    cudaGetSymbolAddress((void**)&kp, g_kp);
    cudaGetSymbolAddress((void**)&vp, g_vp);
    cudaGetSymbolAddress((void**)&ap, g_ap);

    const size_t nIn = (size_t)BB * SS * DD;
    const size_t nW  = (size_t)DD * DD;

    // pack inputs
    pack_kernel<true ><<<(unsigned)(nIn / 4 / 256), 256>>>(query, aq, DD, nIn);
    pack_kernel<true ><<<(unsigned)(nIn / 4 / 256), 256>>>(key,   ak, DD, nIn);
    pack_kernel<false><<<(unsigned)(nW  / 4 / 256), 256>>>(Wq,    wq, DD, nW);
    pack_kernel<false><<<(unsigned)(nW  / 4 / 256), 256>>>(Wk,    wk, DD, nW);
    vpack_kernel<<<dim3(DD / 32, SS / 32, BB), 256>>>(value);

    // projections: q (A-pack out), k (B-pack out)
    gemm_mma<2><<<dim3(DD / BN, (BB * SS) / BM, 1), 256>>>(
        aq, wq, bq, nullptr, nullptr, qp, KPP, 0, 0, 0);
    gemm_mma<3><<<dim3(DD / BN, (BB * SS) / BM, 1), 256>>>(
        ak, wk, bk, nullptr, nullptr, kp, KPP, 0, 0, 0);

    // scores = q k^T + bias -> attn (fp32)
    gemm_mma<1><<<dim3(SS / BN, SS / BM, BB), 256>>>(
        qp, kp, nullptr, attn_bias, attn, nullptr, KPP,
        (size_t)SS * KPP, (size_t)SS * KPP, (size_t)SS * SS);

    // softmax in place + emit packed attention
    softmax_pack_kernel<<<BB * SS, 256>>>(attn);

    // out = attention @ value
    gemm_mma<0><<<dim3(DD / BN, SS / BM, BB), 256>>>(
        ap, vp, nullptr, nullptr, out, nullptr, KPA,
        (size_t)SS * KPA, (size_t)DD * KPA, (size_t)SS * DD);
}

// round 7
// speedup vs baseline: 2.6817x; 1.2016x over previous
#include <cuda_runtime.h>
#include <cuda_bf16.h>
#include <cstdint>
#include <cstddef>

#define BB 16
#define SS 2048
#define DD 512

// ---------------- scratch (__device__ globals, compact [hi|lo] packs) -------
__device__ __align__(256) __nv_bfloat16 g_aq[(size_t)BB * SS * (2 * DD)]; // query  [hi|lo]
__device__ __align__(256) __nv_bfloat16 g_ak[(size_t)BB * SS * (2 * DD)]; // key    [hi|lo]
__device__ __align__(256) __nv_bfloat16 g_wq[(size_t)DD * (2 * DD)];      // Wq     [hi|lo]
__device__ __align__(256) __nv_bfloat16 g_wk[(size_t)DD * (2 * DD)];      // Wk     [hi|lo]
__device__ __align__(256) __nv_bfloat16 g_qp[(size_t)BB * SS * (2 * DD)]; // q proj [hi|lo]
__device__ __align__(256) __nv_bfloat16 g_kp[(size_t)BB * SS * (2 * DD)]; // k proj [hi|lo]
__device__ __align__(256) __nv_bfloat16 g_vp[(size_t)BB * DD * (2 * SS)]; // V^T    [hi|lo]
__device__ __align__(256) __nv_bfloat16 g_ap[(size_t)BB * SS * (2 * SS)]; // attn   [hi|lo]

// ---------------- helpers ---------------------------------------------------
__device__ __forceinline__ uint32_t smem_u32_of(const void* p) {
    uint32_t a;
    asm("{ .reg .u64 t; cvta.to.shared.u64 t, %1; cvt.u32.u64 %0, t; }"
        : "=r"(a) : "l"(p));
    return a;
}
__device__ __forceinline__ void cp_async16(uint32_t dst, const void* src) {
    asm volatile("cp.async.cg.shared.global [%0], [%1], 16;"
                 :: "r"(dst), "l"(src) : "memory");
}
__device__ __forceinline__ void ldsm4(uint32_t (&r)[4], uint32_t addr) {
    asm volatile("ldmatrix.sync.aligned.m8n8.x4.shared.b16 {%0,%1,%2,%3}, [%4];"
                 : "=r"(r[0]), "=r"(r[1]), "=r"(r[2]), "=r"(r[3]) : "r"(addr));
}
__device__ __forceinline__ void mma16816(float (&d)[4], const uint32_t (&a)[4],
                                         uint32_t b0, uint32_t b1) {
    asm volatile("mma.sync.aligned.m16n8k16.row.col.f32.bf16.bf16.f32 "
                 "{%0,%1,%2,%3}, {%4,%5,%6,%7}, {%8,%9}, {%0,%1,%2,%3};"
                 : "+f"(d[0]), "+f"(d[1]), "+f"(d[2]), "+f"(d[3])
                 : "r"(a[0]), "r"(a[1]), "r"(a[2]), "r"(a[3]), "r"(b0), "r"(b1));
}
__device__ __forceinline__ void split2(float v, __nv_bfloat16& h, __nv_bfloat16& l) {
    h = __float2bfloat16(v);
    l = __float2bfloat16(v - __bfloat162float(h));
}

// ---------------- pack fp32 -> compact bf16 [hi|lo] (row stride 2K) ---------
__global__ __launch_bounds__(256)
void pack_kernel(const float* __restrict__ in, __nv_bfloat16* __restrict__ outp,
                 int K, size_t total)
{
    size_t i4 = ((size_t)blockIdx.x * 256 + threadIdx.x) * 4;
    if (i4 >= total) return;
    float4 v = *reinterpret_cast<const float4*>(&in[i4]);
    size_t row = i4 / (size_t)K;
    int col = (int)(i4 - row * K);
    __align__(8) __nv_bfloat16 h[4], l[4];
    split2(v.x, h[0], l[0]); split2(v.y, h[1], l[1]);
    split2(v.z, h[2], l[2]); split2(v.w, h[3], l[3]);
    __nv_bfloat16* rp = outp + row * (size_t)(2 * K) + col;
    *reinterpret_cast<uint2*>(rp)     = *reinterpret_cast<uint2*>(h);
    *reinterpret_cast<uint2*>(rp + K) = *reinterpret_cast<uint2*>(l);
}

// ---------------- value transpose + [hi|lo] pack ----------------------------
// value [B,S,D] fp32 -> g_vp [B, D, 2S]
__global__ __launch_bounds__(256)
void vpack_kernel(const float* __restrict__ value)
{
    __shared__ float t[32][33];
    int b = blockIdx.z, d0 = blockIdx.x * 32, s0 = blockIdx.y * 32;
    const float* vb = value + (size_t)b * SS * DD;
    int tid = threadIdx.x;
    #pragma unroll
    for (int i = 0; i < 4; ++i) {
        int lin = tid + i * 256;
        int r = lin >> 5, c = lin & 31;       // r: s-offset, c: d-offset
        t[r][c] = vb[(size_t)(s0 + r) * DD + d0 + c];
    }
    __syncthreads();
    __nv_bfloat16* ob = g_vp + (size_t)b * DD * (2 * SS);
    #pragma unroll
    for (int i = 0; i < 4; ++i) {
        int lin = tid + i * 256;
        int dr = lin >> 5, sc = lin & 31;
        float v = t[sc][dr];
        __nv_bfloat16 h, l;
        split2(v, h, l);
        size_t base = (size_t)(d0 + dr) * (2 * SS) + (s0 + sc);
        ob[base]      = h;
        ob[base + SS] = l;
    }
}

// ---------------- mma.sync GEMM with hi/lo term decomposition ---------------
// C = (Ah+Al) (Bh+Bl)^T  computed as Ah*Bh + Ah*Bl + Al*Bh (fp32 accum).
// A rows have stride 2R: [hi(R) | lo(R)]. Same for B. Real-K loop over R.
// MODE 0: plain fp32 store (ldc = DD)          -> Cf   (PV)
// MODE 1: + biasm[r*SS + c], fp32 (ldc = SS)   -> Cf   (scores)
// MODE 2: + biasv[c], emit [hi|lo] pack        -> Cp   (projections)
#define BM 128
#define BN 128
#define BKC 32
#define SST 40                               // smem row stride (bf16), 80 B
#define TILE_B (BM * SST * 2)                // one 128x32 tile: 10240 B
#define STAGE_B (4 * TILE_B)                 // Ah, Al, Bh, Bl
#define GSMEM (2 * STAGE_B)                  // 2 stages: 81920 B

__device__ __forceinline__ void stage_load(
    const __nv_bfloat16* __restrict__ A, const __nv_bfloat16* __restrict__ B,
    int R, int row0, int col0, int k0, uint32_t sBase, int tid)
{
    const int ld = 2 * R;
    #pragma unroll
    for (int i = 0; i < 8; ++i) {
        int lin = tid + (i << 8);            // 0..2047
        int t   = lin >> 9;                  // tile 0..3
        int w   = lin & 511;
        int r   = w >> 2, c = w & 3;         // row, 16B-chunk (8 bf16)
        const __nv_bfloat16* src =
            (t < 2) ? (A + (size_t)(row0 + r) * ld + ((t == 1) ? R : 0) + k0 + c * 8)
                    : (B + (size_t)(col0 + r) * ld + ((t == 3) ? R : 0) + k0 + c * 8);
        cp_async16(sBase + t * TILE_B + r * (SST * 2) + c * 16, src);
    }
    asm volatile("cp.async.commit_group;" ::: "memory");
}

template <int MODE>
__global__ __launch_bounds__(256, 2)
void gemm_mma(const __nv_bfloat16* __restrict__ Ag, const __nv_bfloat16* __restrict__ Bg,
              const float* __restrict__ biasv, const float* __restrict__ biasm,
              float* __restrict__ Cf, __nv_bfloat16* __restrict__ Cp,
              int R, size_t sA, size_t sB, size_t sC)
{
    extern __shared__ char dsm[];
    const uint32_t smBase = smem_u32_of(dsm);

    const int tid = threadIdx.x;
    const int wid = tid >> 5, lane = tid & 31;
    const int row0 = blockIdx.y * BM, col0 = blockIdx.x * BN;
    const __nv_bfloat16* A = Ag + (size_t)blockIdx.z * sA;
    const __nv_bfloat16* B = Bg + (size_t)blockIdx.z * sB;
    const int wm = (wid & 3) * 32;      // warp M offset (4 warps)
    const int wn = (wid >> 2) * 64;     // warp N offset (2 warps)

    float acc[2][8][4];
    #pragma unroll
    for (int i = 0; i < 2; ++i)
        #pragma unroll
        for (int j = 0; j < 8; ++j)
            #pragma unroll
            for (int q = 0; q < 4; ++q) acc[i][j][q] = 0.f;

    const int CK = R / BKC;
    stage_load(A, B, R, row0, col0, 0, smBase, tid);

    // precomputed fragment address offsets
    const int arow = wm + (lane & 15);
    const int acolh = (lane >> 4) << 3;
    const int brow = wn + (lane & 7) + ((lane >> 4) << 3);
    const int bcolh = ((lane >> 3) & 1) << 3;

    for (int c = 0; c < CK; ++c) {
        if (c + 1 < CK) {
            stage_load(A, B, R, row0, col0, (c + 1) * BKC,
                       smBase + (uint32_t)((c + 1) & 1) * STAGE_B, tid);
            asm volatile("cp.async.wait_group 1;" ::: "memory");
        } else {
            asm volatile("cp.async.wait_group 0;" ::: "memory");
        }
        __syncthreads();

        const uint32_t st = smBase + (uint32_t)(c & 1) * STAGE_B;
        const uint32_t tAh = st, tAl = st + TILE_B, tBh = st + 2 * TILE_B, tBl = st + 3 * TILE_B;

        #pragma unroll
        for (int kk = 0; kk < 2; ++kk) {
            uint32_t a[2][4], bh[4][4], bl[4][4];
            const int acol = kk * 16 + acolh;
            const int bcol = kk * 16 + bcolh;

            // A_hi fragments
            ldsm4(a[0], tAh + (uint32_t)(arow * (SST * 2) + acol * 2));
            ldsm4(a[1], tAh + (uint32_t)((arow + 16) * (SST * 2) + acol * 2));
            // B_hi fragments
            #pragma unroll
            for (int p = 0; p < 4; ++p)
                ldsm4(bh[p], tBh + (uint32_t)((brow + p * 16) * (SST * 2) + bcol * 2));
            // term 1: Ah * Bh
            #pragma unroll
            for (int mt = 0; mt < 2; ++mt)
                #pragma unroll
                for (int nt = 0; nt < 8; ++nt)
                    mma16816(acc[mt][nt], a[mt],
                             bh[nt >> 1][(nt & 1) * 2], bh[nt >> 1][(nt & 1) * 2 + 1]);
            // B_lo fragments
            #pragma unroll
            for (int p = 0; p < 4; ++p)
                ldsm4(bl[p], tBl + (uint32_t)((brow + p * 16) * (SST * 2) + bcol * 2));
            // term 2: Ah * Bl
            #pragma unroll
            for (int mt = 0; mt < 2; ++mt)
                #pragma unroll
                for (int nt = 0; nt < 8; ++nt)
                    mma16816(acc[mt][nt], a[mt],
                             bl[nt >> 1][(nt & 1) * 2], bl[nt >> 1][(nt & 1) * 2 + 1]);
            // A_lo fragments (reuse registers)
            ldsm4(a[0], tAl + (uint32_t)(arow * (SST * 2) + acol * 2));
            ldsm4(a[1], tAl + (uint32_t)((arow + 16) * (SST * 2) + acol * 2));
            // term 3: Al * Bh
            #pragma unroll
            for (int mt = 0; mt < 2; ++mt)
                #pragma unroll
                for (int nt = 0; nt < 8; ++nt)
                    mma16816(acc[mt][nt], a[mt],
                             bh[nt >> 1][(nt & 1) * 2], bh[nt >> 1][(nt & 1) * 2 + 1]);
        }
        __syncthreads();
    }

    // ---- epilogue ----
    #pragma unroll
    for (int mt = 0; mt < 2; ++mt) {
        #pragma unroll
        for (int h = 0; h < 2; ++h) {
            const int r = row0 + wm + mt * 16 + (lane >> 2) + h * 8;
            if (MODE == 0) {
                float* dst = Cf + (size_t)blockIdx.z * sC + (size_t)r * DD;
                #pragma unroll
                for (int nt = 0; nt < 8; ++nt) {
                    int cg = col0 + wn + nt * 8 + (lane & 3) * 2;
                    float2 v = make_float2(acc[mt][nt][h * 2], acc[mt][nt][h * 2 + 1]);
                    *reinterpret_cast<float2*>(dst + cg) = v;
                }
            } else if (MODE == 1) {
                float* dst = Cf + (size_t)blockIdx.z * sC + (size_t)r * SS;
                const float* bm = biasm + (size_t)r * SS;
                #pragma unroll
                for (int nt = 0; nt < 8; ++nt) {
                    int cg = col0 + wn + nt * 8 + (lane & 3) * 2;
                    float2 b2 = *reinterpret_cast<const float2*>(bm + cg);
                    float2 v = make_float2(acc[mt][nt][h * 2] + b2.x,
                                           acc[mt][nt][h * 2 + 1] + b2.y);
                    *reinterpret_cast<float2*>(dst + cg) = v;
                }
            } else {
                __nv_bfloat16* rp = Cp + (size_t)r * (2 * R);
                #pragma unroll
                for (int nt = 0; nt < 8; ++nt) {
                    int cg = col0 + wn + nt * 8 + (lane & 3) * 2;
                    float2 b2 = *reinterpret_cast<const float2*>(biasv + cg);
                    float vx = acc[mt][nt][h * 2] + b2.x;
                    float vy = acc[mt][nt][h * 2 + 1] + b2.y;
                    __nv_bfloat16 h0, l0, h1, l1;
                    split2(vx, h0, l0); split2(vy, h1, l1);
                    *reinterpret_cast<__nv_bfloat162*>(rp + cg)     = __nv_bfloat162(h0, h1);
                    *reinterpret_cast<__nv_bfloat162*>(rp + R + cg) = __nv_bfloat162(l0, l1);
                }
            }
        }
    }
}

// ---------------- softmax + compact [hi|lo] pack emit -----------------------
__global__ __launch_bounds__(256)
void softmax_pack_kernel(float* __restrict__ attn)
{
    const size_t row = blockIdx.x;
    float* p = attn + row * (size_t)SS;
    const int t = threadIdx.x;
    const int lane = t & 31, warp = t >> 5;

    float v[8];
    float4 a = *reinterpret_cast<const float4*>(&p[t * 8]);
    float4 b = *reinterpret_cast<const float4*>(&p[t * 8 + 4]);
    v[0] = a.x; v[1] = a.y; v[2] = a.z; v[3] = a.w;
    v[4] = b.x; v[5] = b.y; v[6] = b.z; v[7] = b.w;

    __shared__ float red[8];
    __shared__ float bc[2];

    float m = v[0];
    #pragma unroll
    for (int i = 1; i < 8; ++i) m = fmaxf(m, v[i]);
    #pragma unroll
    for (int off = 16; off > 0; off >>= 1)
        m = fmaxf(m, __shfl_xor_sync(0xFFFFFFFFu, m, off));
    if (lane == 0) red[warp] = m;
    __syncthreads();
    if (t == 0) {
        float mm = red[0];
        #pragma unroll
        for (int w = 1; w < 8; ++w) mm = fmaxf(mm, red[w]);
        bc[0] = mm;
    }
    __syncthreads();
    const float rmax = bc[0];

    float s = 0.f;
    #pragma unroll
    for (int i = 0; i < 8; ++i) { v[i] = __expf(v[i] - rmax); s += v[i]; }
    #pragma unroll
    for (int off = 16; off > 0; off >>= 1)
        s += __shfl_xor_sync(0xFFFFFFFFu, s, off);
    __syncthreads();
    if (lane == 0) red[warp] = s;
    __syncthreads();
    if (t == 0) {
        float ss = red[0];
        #pragma unroll
        for (int w = 1; w < 8; ++w) ss += red[w];
        bc[1] = 1.f / ss;
    }
    __syncthreads();
    const float inv = bc[1];

    __align__(16) __nv_bfloat16 h8[8], l8[8];
    #pragma unroll
    for (int i = 0; i < 8; ++i) {
        v[i] *= inv;
        split2(v[i], h8[i], l8[i]);
    }
    *reinterpret_cast<float4*>(&p[t * 8])     = make_float4(v[0], v[1], v[2], v[3]);
    *reinterpret_cast<float4*>(&p[t * 8 + 4]) = make_float4(v[4], v[5], v[6], v[7]);

    size_t base = row * (size_t)(2 * SS) + t * 8;
    *reinterpret_cast<uint4*>(&g_ap[base])      = *reinterpret_cast<uint4*>(h8);
    *reinterpret_cast<uint4*>(&g_ap[base + SS]) = *reinterpret_cast<uint4*>(l8);
}

// ---------------- host launcher ---------------------------------------------
extern "C" void kernel_launch(void* const* d_in, const int* in_sizes, int n_in,
                              void* d_out, int out_size)
{
    (void)in_sizes; (void)n_in; (void)out_size;
    const float* query     = (const float*)d_in[0];
    const float* key       = (const float*)d_in[1];
    const float* value     = (const float*)d_in[2];
    const float* attn_bias = (const float*)d_in[3];
    const float* Wq        = (const float*)d_in[4];
    const float* bq        = (const float*)d_in[5];
    const float* Wk        = (const float*)d_in[6];
    const float* bk        = (const float*)d_in[7];

    float* out  = (float*)d_out;
    float* attn = out + (size_t)BB * SS * DD;

    __nv_bfloat16 *aq, *ak, *wq, *wk, *qp, *kp, *vp, *ap;
    cudaGetSymbolAddress((void**)&aq, g_aq);
    cudaGetSymbolAddress((void**)&ak, g_ak);
    cudaGetSymbolAddress((void**)&wq, g_wq);
    cudaGetSymbolAddress((void**)&wk, g_wk);
    cudaGetSymbolAddress((void**)&qp, g_qp);
    cudaGetSymbolAddress((void**)&kp, g_kp);
    cudaGetSymbolAddress((void**)&vp, g_vp);
    cudaGetSymbolAddress((void**)&ap, g_ap);

    cudaFuncSetAttribute(gemm_mma<0>, cudaFuncAttributeMaxDynamicSharedMemorySize, GSMEM);
    cudaFuncSetAttribute(gemm_mma<1>, cudaFuncAttributeMaxDynamicSharedMemorySize, GSMEM);
    cudaFuncSetAttribute(gemm_mma<2>, cudaFuncAttributeMaxDynamicSharedMemorySize, GSMEM);

    const size_t nIn = (size_t)BB * SS * DD;
    const size_t nW  = (size_t)DD * DD;

    // pack inputs to compact [hi|lo]
    pack_kernel<<<(unsigned)(nIn / 4 / 256), 256>>>(query, aq, DD, nIn);
    pack_kernel<<<(unsigned)(nIn / 4 / 256), 256>>>(key,   ak, DD, nIn);
    pack_kernel<<<(unsigned)(nW  / 4 / 256), 256>>>(Wq,    wq, DD, nW);
    pack_kernel<<<(unsigned)(nW  / 4 / 256), 256>>>(Wk,    wk, DD, nW);
    vpack_kernel<<<dim3(DD / 32, SS / 32, BB), 256>>>(value);

    // projections: emit compact packs
    gemm_mma<2><<<dim3(DD / BN, (BB * SS) / BM, 1), 256, GSMEM>>>(
        aq, wq, bq, nullptr, nullptr, qp, DD, 0, 0, 0);
    gemm_mma<2><<<dim3(DD / BN, (BB * SS) / BM, 1), 256, GSMEM>>>(
        ak, wk, bk, nullptr, nullptr, kp, DD, 0, 0, 0);

    // scores = q k^T + bias -> attn (fp32)
    gemm_mma<1><<<dim3(SS / BN, SS / BM, BB), 256, GSMEM>>>(
        qp, kp, nullptr, attn_bias, attn, nullptr, DD,
        (size_t)SS * (2 * DD), (size_t)SS * (2 * DD), (size_t)SS * SS);

    // softmax in place + emit compact attention pack
    softmax_pack_kernel<<<BB * SS, 256>>>(attn);

    // out = attention @ value
    gemm_mma<0><<<dim3(DD / BN, SS / BM, BB), 256, GSMEM>>>(
        ap, vp, nullptr, nullptr, out, nullptr, SS,
        (size_t)SS * (2 * SS), (size_t)DD * (2 * SS), (size_t)SS * DD);
}